// round 3
// baseline (speedup 1.0000x reference)
#include <cuda_runtime.h>
#include <math.h>

#define NNODES 16000
#define DIN    256
#define HD     256   // H*D
#define NH     8
#define DH     32
#define NEDGES 256000

// --- device scratch (no allocations allowed) ---
__device__ float g_q[NNODES * HD];
__device__ float g_k[NNODES * HD];
__device__ float g_v[NNODES * HD];
__device__ float g_wV[NNODES * HD];
__device__ float g_z[NNODES * NH];

// ---------------------------------------------------------------------------
// zero accumulators + copy coords to output
// ---------------------------------------------------------------------------
__global__ void zero_kernel(const float* __restrict__ coords,
                            float* __restrict__ cout) {
    int i = blockIdx.x * blockDim.x + threadIdx.x;
    if (i < NNODES * HD) g_wV[i] = 0.0f;
    if (i < NNODES * NH) g_z[i] = 0.0f;
    if (i < NNODES * 3)  cout[i] = coords[i];
}

// ---------------------------------------------------------------------------
// QKV GEMM: C[16000 x 768] = x[16000 x 256] @ [Wq | Wk | Wv]
// 64x64 tiles, BK=32, 256 threads, 4x4 per thread.
// ---------------------------------------------------------------------------
__global__ __launch_bounds__(256) void qkv_gemm(
    const float* __restrict__ x,
    const float* __restrict__ Wq,
    const float* __restrict__ Wk,
    const float* __restrict__ Wv)
{
    __shared__ float sA[32][65];   // transposed: sA[k][m]
    __shared__ float sB[32][64];

    int bx = blockIdx.x;           // 0..11 : which 64-col tile of [q|k|v]
    int by = blockIdx.y;           // 0..249
    const float* W   = (bx < 4) ? Wq : (bx < 8) ? Wk : Wv;
    float*       out = (bx < 4) ? g_q : (bx < 8) ? g_k : g_v;
    int n0 = (bx & 3) * 64;
    int m0 = by * 64;

    int tid = threadIdx.x;
    int tx = tid & 15, ty = tid >> 4;

    float acc[4][4] = {};

    for (int k0 = 0; k0 < DIN; k0 += 32) {
        // load A tile (64 rows x 32 k), transposed
        {
            int c = tid & 31, rb = tid >> 5;   // rb 0..7
            #pragma unroll
            for (int p = 0; p < 8; ++p) {
                int r = rb + p * 8;
                sA[c][r] = x[(m0 + r) * DIN + k0 + c];
            }
        }
        // load B tile (32 x 64)
        {
            int c = tid & 63, rb = tid >> 6;   // rb 0..3
            #pragma unroll
            for (int p = 0; p < 8; ++p) {
                int r = rb + p * 4;
                sB[r][c] = W[(k0 + r) * HD + n0 + c];
            }
        }
        __syncthreads();

        #pragma unroll 8
        for (int kk = 0; kk < 32; ++kk) {
            float a[4], b[4];
            #pragma unroll
            for (int ii = 0; ii < 4; ++ii) a[ii] = sA[kk][ty + 16 * ii];
            #pragma unroll
            for (int jj = 0; jj < 4; ++jj) b[jj] = sB[kk][tx + 16 * jj];
            #pragma unroll
            for (int ii = 0; ii < 4; ++ii)
                #pragma unroll
                for (int jj = 0; jj < 4; ++jj)
                    acc[ii][jj] += a[ii] * b[jj];
        }
        __syncthreads();
    }

    #pragma unroll
    for (int ii = 0; ii < 4; ++ii)
        #pragma unroll
        for (int jj = 0; jj < 4; ++jj)
            out[(m0 + ty + 16 * ii) * HD + n0 + tx + 16 * jj] = acc[ii][jj];
}

// ---------------------------------------------------------------------------
// Edge kernel: per block handles 64 edges x all 256 output cols.
//   ea  = edge_attr @ We[0:256] + dist * We[256]
//   s   = clip(k[src]*q[dst]/sqrt(32), -5, 5)
//   alpha = s * ea   -> e_out
//   ax  = exp(clip(sum_d alpha, -5, 5))   (warp shuffle reduction per head)
//   atomicAdd wV[dst] += v[src]*ax ; z[dst] += ax
// ---------------------------------------------------------------------------
__global__ __launch_bounds__(256) void edge_kernel(
    const float* __restrict__ edge_attr,
    const int* __restrict__ ei,
    const float* __restrict__ coords,
    const float* __restrict__ We,
    float* __restrict__ e_out)
{
    __shared__ float sA[64][33];
    __shared__ float sB[32][256];
    __shared__ int   sSrc[64], sDst[64];
    __shared__ float sDist[64];
    __shared__ float sAx[64][NH];

    int tid = threadIdx.x;
    int e0  = blockIdx.x * 64;

    if (tid < 64) {
        int s = ei[e0 + tid];
        int d = ei[NEDGES + e0 + tid];
        sSrc[tid] = s;
        sDst[tid] = d;
        float dx = coords[3 * s + 0] - coords[3 * d + 0];
        float dy = coords[3 * s + 1] - coords[3 * d + 1];
        float dz = coords[3 * s + 2] - coords[3 * d + 2];
        sDist[tid] = 0.1f * sqrtf(dx * dx + dy * dy + dz * dz);
    }

    int tx = tid & 63, ty = tid >> 6;
    float acc[16][4] = {};

    for (int k0 = 0; k0 < DIN; k0 += 32) {
        // load edge_attr tile 64 x 32
        {
            int c = tid & 31, rb = tid >> 5;
            #pragma unroll
            for (int p = 0; p < 8; ++p) {
                int r = rb + p * 8;
                sA[r][c] = edge_attr[(e0 + r) * DIN + k0 + c];
            }
        }
        // load We tile 32 x 256
        #pragma unroll 8
        for (int r = 0; r < 32; ++r)
            sB[r][tid] = We[(k0 + r) * HD + tid];
        __syncthreads();

        #pragma unroll 4
        for (int kk = 0; kk < 32; ++kk) {
            float b[4];
            #pragma unroll
            for (int j = 0; j < 4; ++j) b[j] = sB[kk][tx + 64 * j];
            #pragma unroll
            for (int i = 0; i < 16; ++i) {
                float a = sA[ty + 4 * i][kk];
                #pragma unroll
                for (int j = 0; j < 4; ++j) acc[i][j] += a * b[j];
            }
        }
        __syncthreads();
    }

    // extra feature row of We (dist coefficient)
    float wlast[4];
    #pragma unroll
    for (int j = 0; j < 4; ++j) wlast[j] = We[DIN * HD + tx + 64 * j];

    const float invs = 0.17677669529663687f;   // 1/sqrt(32)
    int hi = tx >> 5;                           // which half of the 64-col group

    #pragma unroll
    for (int i = 0; i < 16; ++i) {
        int e   = ty + 4 * i;
        int src = sSrc[e];
        int dst = sDst[e];
        float de = sDist[e];
        #pragma unroll
        for (int j = 0; j < 4; ++j) {
            int c = tx + 64 * j;
            float ea = acc[i][j] + de * wlast[j];
            float kv = g_k[src * HD + c];
            float qv = g_q[dst * HD + c];
            float s  = kv * qv * invs;
            s = fminf(5.0f, fmaxf(-5.0f, s));
            float alpha = s * ea;
            e_out[(e0 + e) * HD + c] = alpha;

            // warp reduction over the 32 d-values of head (2j + hi)
            float sum = alpha;
            #pragma unroll
            for (int o = 16; o; o >>= 1)
                sum += __shfl_xor_sync(0xffffffffu, sum, o);
            if ((tid & 31) == 0) {
                float cs = fminf(5.0f, fmaxf(-5.0f, sum));
                sAx[e][2 * j + hi] = expf(cs);
            }
        }
    }
    __syncthreads();

    // scatter-add wV and z
    #pragma unroll
    for (int i = 0; i < 16; ++i) {
        int e   = ty + 4 * i;
        int src = sSrc[e];
        int dst = sDst[e];
        #pragma unroll
        for (int j = 0; j < 4; ++j) {
            int c = tx + 64 * j;
            float ax = sAx[e][2 * j + hi];
            float vv = g_v[src * HD + c];
            atomicAdd(&g_wV[dst * HD + c], vv * ax);
        }
    }
    for (int p = tid; p < 64 * NH; p += 256) {
        int e = p >> 3, h = p & 7;
        atomicAdd(&g_z[sDst[e] * NH + h], sAx[e][h]);
    }
}

// ---------------------------------------------------------------------------
// finalize: h_out = wV / (z + 1e-6)
// ---------------------------------------------------------------------------
__global__ void finalize_kernel(float* __restrict__ hout) {
    int i = blockIdx.x * blockDim.x + threadIdx.x;
    if (i < NNODES * HD) {
        int n = i >> 8;
        int h = (i & 255) >> 5;
        hout[i] = g_wV[i] / (g_z[n * NH + h] + 1e-6f);
    }
}

// ---------------------------------------------------------------------------
extern "C" void kernel_launch(void* const* d_in, const int* in_sizes, int n_in,
                              void* d_out, int out_size)
{
    const float* x         = (const float*)d_in[0];
    const float* edge_attr = (const float*)d_in[1];
    const int*   ei        = (const int*)d_in[2];
    const float* coords    = (const float*)d_in[3];
    const float* Wq        = (const float*)d_in[4];
    const float* Wk        = (const float*)d_in[5];
    const float* Wv        = (const float*)d_in[6];
    const float* We        = (const float*)d_in[7];

    float* out  = (float*)d_out;
    float* hout = out;                                   // [N, H, D]
    float* eout = out + (size_t)NNODES * HD;             // [E, H, D]
    float* cout = eout + (size_t)NEDGES * HD;            // [N, 3]

    zero_kernel<<<(NNODES * HD + 255) / 256, 256>>>(coords, cout);
    qkv_gemm<<<dim3(12, 250), 256>>>(x, Wq, Wk, Wv);
    edge_kernel<<<NEDGES / 64, 256>>>(edge_attr, ei, coords, We, eout);
    finalize_kernel<<<(NNODES * HD + 255) / 256, 256>>>(hout);
}

// round 5
// speedup vs baseline: 1.4534x; 1.4534x over previous
#include <cuda_runtime.h>
#include <cuda_bf16.h>
#include <math.h>
#include <stdint.h>

#define NNODES 16000
#define DIN    256
#define HD     256
#define NH     8
#define NEDGES 256000

// ---------------- device scratch ----------------
__device__ float g_q[NNODES * HD];
__device__ float g_k[NNODES * HD];
__device__ float g_v[NNODES * HD];
__device__ float g_wV[NNODES * HD];
__device__ float g_z[NNODES * NH];
// transposed bf16 weight images: [mat][n=256][k=256]; mat: 0=Wq 1=Wk 2=Wv 3=We
__device__ __nv_bfloat16 g_Bth[4][256 * 256];
__device__ __nv_bfloat16 g_Btl[4][256 * 256];

// ---------------- mma helper ----------------
__device__ __forceinline__ void mma16816(float* d, const uint32_t* a, const uint32_t* b) {
    asm volatile(
        "mma.sync.aligned.m16n8k16.row.col.f32.bf16.bf16.f32 "
        "{%0,%1,%2,%3}, {%4,%5,%6,%7}, {%8,%9}, {%0,%1,%2,%3};"
        : "+f"(d[0]), "+f"(d[1]), "+f"(d[2]), "+f"(d[3])
        : "r"(a[0]), "r"(a[1]), "r"(a[2]), "r"(a[3]), "r"(b[0]), "r"(b[1]));
}

// SMEM layout (bytes). A/B tiles use element-stride 40 (80B rows) for
// conflict-free fragment LDS.
#define SM_SRC   0
#define SM_DST   512
#define SM_DIST  1024
#define SM_AX    1536     // 128*8 floats
#define SM_AHI   6144     // 128 rows * 80B
#define SM_ALO   16384
#define SM_BHI   26624    // 256 rows * 80B
#define SM_BLO   47104
#define SM_TOTAL 67584

// ---------------------------------------------------------------------------
__global__ void zero_kernel(const float* __restrict__ coords, float* __restrict__ cout) {
    int i = blockIdx.x * blockDim.x + threadIdx.x;
    if (i < NNODES * HD) g_wV[i] = 0.0f;
    if (i < NNODES * NH) g_z[i] = 0.0f;
    if (i < NNODES * 3)  cout[i] = coords[i];
}

// ---------------------------------------------------------------------------
// Weight prep: W[k][n] fp32 -> g_Bt{h,l}[mat][n][k] bf16 (hi/lo split).
// t = (mat, n, ku) ; ku = 8-k unit.
// ---------------------------------------------------------------------------
__global__ void prep_weights(const float* __restrict__ Wq, const float* __restrict__ Wk,
                             const float* __restrict__ Wv, const float* __restrict__ We) {
    int t = blockIdx.x * blockDim.x + threadIdx.x;
    if (t >= 4 * 256 * 32) return;
    int mat = t >> 13;
    int rem = t & 8191;
    int n   = rem >> 5;
    int ku  = rem & 31;
    const float* W = mat == 0 ? Wq : mat == 1 ? Wk : mat == 2 ? Wv : We;
    uint32_t h[4], l[4];
    #pragma unroll
    for (int p = 0; p < 4; ++p) {
        float f0 = W[(ku * 8 + 2 * p) * HD + n];
        float f1 = W[(ku * 8 + 2 * p + 1) * HD + n];
        __nv_bfloat162 hh = __floats2bfloat162_rn(f0, f1);
        float l0 = f0 - __bfloat162float(hh.x);
        float l1 = f1 - __bfloat162float(hh.y);
        __nv_bfloat162 ll = __floats2bfloat162_rn(l0, l1);
        h[p] = *(uint32_t*)&hh;
        l[p] = *(uint32_t*)&ll;
    }
    *(uint4*)&g_Bth[mat][n * 256 + ku * 8] = make_uint4(h[0], h[1], h[2], h[3]);
    *(uint4*)&g_Btl[mat][n * 256 + ku * 8] = make_uint4(l[0], l[1], l[2], l[3]);
}

// ---------------------------------------------------------------------------
// GEMM mainloop: acc[4][8][4] += split-bf16( A[m0:128, :256] @ W^T )
// 256 threads, 8 warps (2 x 4); warp tile 64x64.
// ---------------------------------------------------------------------------
__device__ __forceinline__ void gemm_tile(char* smem, const float* __restrict__ A, int m0,
                                          int mat, int tid, float acc[4][8][4]) {
    int lane = tid & 31, w = tid >> 5;
    int warp_m = w & 1, warp_n = w >> 1;
    int qrow = lane >> 2, qcol = lane & 3;
    const __nv_bfloat16* Bh = g_Bth[mat];
    const __nv_bfloat16* Bl = g_Btl[mat];

    for (int kc = 0; kc < 8; ++kc) {
        // --- load A chunk: 128 rows x 32 k, fp32 -> hi/lo bf16 ---
        #pragma unroll
        for (int i = 0; i < 2; ++i) {
            int un = tid + 256 * i;       // 0..511
            int r = un >> 2, u = un & 3;  // 8 k per unit
            const float4* src = (const float4*)(A + (size_t)(m0 + r) * DIN + kc * 32 + u * 8);
            float4 f0 = src[0], f1 = src[1];
            float fv[8] = {f0.x, f0.y, f0.z, f0.w, f1.x, f1.y, f1.z, f1.w};
            uint32_t h[4], l[4];
            #pragma unroll
            for (int p = 0; p < 4; ++p) {
                __nv_bfloat162 hh = __floats2bfloat162_rn(fv[2 * p], fv[2 * p + 1]);
                float l0 = fv[2 * p] - __bfloat162float(hh.x);
                float l1 = fv[2 * p + 1] - __bfloat162float(hh.y);
                __nv_bfloat162 ll = __floats2bfloat162_rn(l0, l1);
                h[p] = *(uint32_t*)&hh;
                l[p] = *(uint32_t*)&ll;
            }
            *(uint4*)(smem + SM_AHI + r * 80 + u * 16) = make_uint4(h[0], h[1], h[2], h[3]);
            *(uint4*)(smem + SM_ALO + r * 80 + u * 16) = make_uint4(l[0], l[1], l[2], l[3]);
        }
        // --- load B chunk: 256 n x 32 k (pre-split bf16, 16B copies) ---
        #pragma unroll
        for (int i = 0; i < 4; ++i) {
            int un = tid + 256 * i;       // 0..1023
            int n = un >> 2, u = un & 3;
            *(uint4*)(smem + SM_BHI + n * 80 + u * 16) = *(const uint4*)&Bh[n * 256 + kc * 32 + u * 8];
            *(uint4*)(smem + SM_BLO + n * 80 + u * 16) = *(const uint4*)&Bl[n * 256 + kc * 32 + u * 8];
        }
        __syncthreads();

        #pragma unroll
        for (int ks = 0; ks < 2; ++ks) {
            uint32_t ah[4][4], al[4][4];
            #pragma unroll
            for (int mf = 0; mf < 4; ++mf) {
                int base = (warp_m * 64 + mf * 16 + qrow) * 80 + qcol * 4 + ks * 32;
                ah[mf][0] = *(const uint32_t*)(smem + SM_AHI + base);
                ah[mf][1] = *(const uint32_t*)(smem + SM_AHI + base + 640);
                ah[mf][2] = *(const uint32_t*)(smem + SM_AHI + base + 16);
                ah[mf][3] = *(const uint32_t*)(smem + SM_AHI + base + 656);
                al[mf][0] = *(const uint32_t*)(smem + SM_ALO + base);
                al[mf][1] = *(const uint32_t*)(smem + SM_ALO + base + 640);
                al[mf][2] = *(const uint32_t*)(smem + SM_ALO + base + 16);
                al[mf][3] = *(const uint32_t*)(smem + SM_ALO + base + 656);
            }
            #pragma unroll
            for (int nf = 0; nf < 8; ++nf) {
                int nb = (warp_n * 64 + nf * 8 + qrow) * 80 + qcol * 4 + ks * 32;
                uint32_t bh[2], bl[2];
                bh[0] = *(const uint32_t*)(smem + SM_BHI + nb);
                bh[1] = *(const uint32_t*)(smem + SM_BHI + nb + 16);
                bl[0] = *(const uint32_t*)(smem + SM_BLO + nb);
                bl[1] = *(const uint32_t*)(smem + SM_BLO + nb + 16);
                #pragma unroll
                for (int mf = 0; mf < 4; ++mf) {
                    mma16816(acc[mf][nf], ah[mf], bh);
                    mma16816(acc[mf][nf], al[mf], bh);
                    mma16816(acc[mf][nf], ah[mf], bl);
                }
            }
        }
        __syncthreads();
    }
}

// ---------------------------------------------------------------------------
// QKV GEMM. grid (125, 3)
// ---------------------------------------------------------------------------
__global__ __launch_bounds__(256, 1) void qkv_mm(const float* __restrict__ x) {
    extern __shared__ char smem[];
    int tid = threadIdx.x;
    int m0 = blockIdx.x * 128;
    int mat = blockIdx.y;

    float acc[4][8][4];
    #pragma unroll
    for (int mf = 0; mf < 4; ++mf)
        #pragma unroll
        for (int nf = 0; nf < 8; ++nf)
            #pragma unroll
            for (int p = 0; p < 4; ++p) acc[mf][nf][p] = 0.0f;

    gemm_tile(smem, x, m0, mat, tid, acc);

    int lane = tid & 31, w = tid >> 5;
    int warp_m = w & 1, warp_n = w >> 1;
    int qrow = lane >> 2, qcol = lane & 3;
    float* out = mat == 0 ? g_q : mat == 1 ? g_k : g_v;

    #pragma unroll
    for (int mf = 0; mf < 4; ++mf) {
        int r0 = m0 + warp_m * 64 + mf * 16 + qrow;
        #pragma unroll
        for (int nf = 0; nf < 8; ++nf) {
            int c = warp_n * 64 + nf * 8 + qcol * 2;
            *(float2*)(out + (size_t)r0 * HD + c)       = make_float2(acc[mf][nf][0], acc[mf][nf][1]);
            *(float2*)(out + (size_t)(r0 + 8) * HD + c) = make_float2(acc[mf][nf][2], acc[mf][nf][3]);
        }
    }
}

// ---------------------------------------------------------------------------
// Edge GEMM + fused attention epilogue. grid 2000.
// ---------------------------------------------------------------------------
__global__ __launch_bounds__(256, 1) void edge_mm(const float* __restrict__ edge_attr,
                                                  const int* __restrict__ ei,
                                                  const float* __restrict__ coords,
                                                  const float* __restrict__ We,
                                                  float* __restrict__ eout) {
    extern __shared__ char smem[];
    int tid = threadIdx.x;
    int m0 = blockIdx.x * 128;

    int*   sSrc = (int*)(smem + SM_SRC);
    int*   sDst = (int*)(smem + SM_DST);
    float* sDist = (float*)(smem + SM_DIST);
    float* sAx  = (float*)(smem + SM_AX);

    if (tid < 128) {
        int s = ei[m0 + tid];
        int d = ei[NEDGES + m0 + tid];
        sSrc[tid] = s; sDst[tid] = d;
        float dx = coords[3 * s + 0] - coords[3 * d + 0];
        float dy = coords[3 * s + 1] - coords[3 * d + 1];
        float dz = coords[3 * s + 2] - coords[3 * d + 2];
        sDist[tid] = 0.1f * sqrtf(dx * dx + dy * dy + dz * dz);
    }
    __syncthreads();

    float acc[4][8][4];
    #pragma unroll
    for (int mf = 0; mf < 4; ++mf)
        #pragma unroll
        for (int nf = 0; nf < 8; ++nf)
            #pragma unroll
            for (int p = 0; p < 4; ++p) acc[mf][nf][p] = 0.0f;

    gemm_tile(smem, edge_attr, m0, 3, tid, acc);

    int lane = tid & 31, w = tid >> 5;
    int warp_m = w & 1, warp_n = w >> 1;
    int qrow = lane >> 2, qcol = lane & 3;
    const float invs = 0.17677669529663687f;   // 1/sqrt(32)

    #pragma unroll
    for (int mf = 0; mf < 4; ++mf) {
        int erow0 = warp_m * 64 + mf * 16 + qrow;
        #pragma unroll
        for (int half = 0; half < 2; ++half) {
            int e = erow0 + 8 * half;
            int src = sSrc[e], dst = sDst[e];
            float de = sDist[e];
            float hsum0 = 0.0f, hsum1 = 0.0f;
            #pragma unroll
            for (int nf = 0; nf < 8; ++nf) {
                int c = warp_n * 64 + nf * 8 + qcol * 2;
                float2 kk = *(const float2*)(g_k + (size_t)src * HD + c);
                float2 qq = *(const float2*)(g_q + (size_t)dst * HD + c);
                float2 wl = *(const float2*)(We + (size_t)DIN * HD + c);
                float d0 = acc[mf][nf][2 * half + 0];
                float d1 = acc[mf][nf][2 * half + 1];
                float s0 = fminf(5.0f, fmaxf(-5.0f, kk.x * qq.x * invs));
                float s1 = fminf(5.0f, fmaxf(-5.0f, kk.y * qq.y * invs));
                float a0 = s0 * (d0 + de * wl.x);
                float a1 = s1 * (d1 + de * wl.y);
                *(float2*)(eout + (size_t)(m0 + e) * HD + c) = make_float2(a0, a1);
                if (nf < 4) hsum0 += a0 + a1; else hsum1 += a0 + a1;
            }
            // quad reduction (lanes sharing qrow)
            hsum0 += __shfl_xor_sync(0xffffffffu, hsum0, 1);
            hsum0 += __shfl_xor_sync(0xffffffffu, hsum0, 2);
            hsum1 += __shfl_xor_sync(0xffffffffu, hsum1, 1);
            hsum1 += __shfl_xor_sync(0xffffffffu, hsum1, 2);
            if (qcol == 0) {
                float ax0 = expf(fminf(5.0f, fmaxf(-5.0f, hsum0)));
                float ax1 = expf(fminf(5.0f, fmaxf(-5.0f, hsum1)));
                int h0 = 2 * warp_n, h1 = h0 + 1;
                sAx[e * NH + h0] = ax0;
                sAx[e * NH + h1] = ax1;
                atomicAdd(&g_z[(size_t)dst * NH + h0], ax0);
                atomicAdd(&g_z[(size_t)dst * NH + h1], ax1);
            }
        }
    }
    __syncthreads();

    // scatter wV += v[src] * ax : 1024 (edge, head) pairs over 256 threads
    #pragma unroll
    for (int i = 0; i < 4; ++i) {
        int p = tid + 256 * i;
        int e = p >> 3, h = p & 7;
        int src = sSrc[e], dst = sDst[e];
        float ax = sAx[e * NH + h];
        const float4* v4 = (const float4*)(g_v + (size_t)src * HD + h * 32);
        float* wv = g_wV + (size_t)dst * HD + h * 32;
        #pragma unroll
        for (int j = 0; j < 8; ++j) {
            float4 vv = v4[j];
            atomicAdd(wv + 4 * j + 0, vv.x * ax);
            atomicAdd(wv + 4 * j + 1, vv.y * ax);
            atomicAdd(wv + 4 * j + 2, vv.z * ax);
            atomicAdd(wv + 4 * j + 3, vv.w * ax);
        }
    }
}

// ---------------------------------------------------------------------------
__global__ void finalize_kernel(float* __restrict__ hout) {
    int i = blockIdx.x * blockDim.x + threadIdx.x;
    if (i < NNODES * HD) {
        int n = i >> 8;
        int h = (i & 255) >> 5;
        hout[i] = g_wV[i] / (g_z[n * NH + h] + 1e-6f);
    }
}

// ---------------------------------------------------------------------------
extern "C" void kernel_launch(void* const* d_in, const int* in_sizes, int n_in,
                              void* d_out, int out_size)
{
    const float* x         = (const float*)d_in[0];
    const float* edge_attr = (const float*)d_in[1];
    const int*   ei        = (const int*)d_in[2];
    const float* coords    = (const float*)d_in[3];
    const float* Wq        = (const float*)d_in[4];
    const float* Wk        = (const float*)d_in[5];
    const float* Wv        = (const float*)d_in[6];
    const float* We        = (const float*)d_in[7];

    float* out  = (float*)d_out;
    float* hout = out;
    float* eout = out + (size_t)NNODES * HD;
    float* cout = eout + (size_t)NEDGES * HD;

    static bool attr_set = false;
    if (!attr_set) {
        cudaFuncSetAttribute(qkv_mm,  cudaFuncAttributeMaxDynamicSharedMemorySize, SM_TOTAL);
        cudaFuncSetAttribute(edge_mm, cudaFuncAttributeMaxDynamicSharedMemorySize, SM_TOTAL);
        attr_set = true;
    }

    zero_kernel<<<(NNODES * HD + 255) / 256, 256>>>(coords, cout);
    prep_weights<<<128, 256>>>(Wq, Wk, Wv, We);
    qkv_mm<<<dim3(125, 3), 256, SM_TOTAL>>>(x);
    edge_mm<<<2000, 256, SM_TOTAL>>>(edge_attr, ei, coords, We, eout);
    finalize_kernel<<<(NNODES * HD + 255) / 256, 256>>>(hout);
}

// round 6
// speedup vs baseline: 1.8256x; 1.2560x over previous
#include <cuda_runtime.h>
#include <cuda_bf16.h>
#include <math.h>
#include <stdint.h>

#define NNODES 16000
#define DIN    256
#define HD     256
#define NH     8
#define NEDGES 256000

// ---------------- device scratch ----------------
__device__ float g_q[NNODES * HD];
__device__ float g_k[NNODES * HD];
__device__ float g_v[NNODES * HD];
__device__ float g_wV[NNODES * HD];
__device__ float g_z[NNODES * NH];
// transposed bf16 weight images: [mat][n=256][k=256]; mat: 0=Wq 1=Wk 2=Wv 3=We
__device__ __nv_bfloat16 g_Bth[4][256 * 256];
__device__ __nv_bfloat16 g_Btl[4][256 * 256];

// ---------------- helpers ----------------
__device__ __forceinline__ void mma16816(float* d, const uint32_t* a, const uint32_t* b) {
    asm volatile(
        "mma.sync.aligned.m16n8k16.row.col.f32.bf16.bf16.f32 "
        "{%0,%1,%2,%3}, {%4,%5,%6,%7}, {%8,%9}, {%0,%1,%2,%3};"
        : "+f"(d[0]), "+f"(d[1]), "+f"(d[2]), "+f"(d[3])
        : "r"(a[0]), "r"(a[1]), "r"(a[2]), "r"(a[3]), "r"(b[0]), "r"(b[1]));
}
__device__ __forceinline__ uint32_t smem_u32(const void* p) {
    uint32_t a;
    asm("{ .reg .u64 t; cvta.to.shared.u64 t, %1; cvt.u32.u64 %0, t; }" : "=r"(a) : "l"(p));
    return a;
}
__device__ __forceinline__ void cp_async16(uint32_t dst, const void* src) {
    asm volatile("cp.async.cg.shared.global [%0], [%1], 16;" :: "r"(dst), "l"(src));
}
#define CP_COMMIT asm volatile("cp.async.commit_group;" ::: "memory")
#define CP_WAIT0  asm volatile("cp.async.wait_group 0;" ::: "memory")

// SMEM layout (bytes). A/B tiles use 80B rows (conflict-free fragment LDS).
#define SM_SRC   0
#define SM_DST   512
#define SM_DIST  1024
#define SM_AX    1536      // 128*8 floats = 4096
#define SM_A     5632      // 2 bufs x (hi 10240 + lo 10240)
#define ABUF     20480
#define SM_B     46592     // 2 bufs x (hi 20480 + lo 20480)
#define BBUF     40960
#define SM_TOTAL 128512

// ---------------------------------------------------------------------------
__global__ void zero_kernel(const float* __restrict__ coords, float* __restrict__ cout) {
    int i = blockIdx.x * blockDim.x + threadIdx.x;
    if (i < NNODES * HD) g_wV[i] = 0.0f;
    if (i < NNODES * NH) g_z[i] = 0.0f;
    if (i < NNODES * 3)  cout[i] = coords[i];
}

// ---------------------------------------------------------------------------
// Weight prep: W[k][n] fp32 -> g_Bt{h,l}[mat][n][k] bf16 (hi/lo split).
// ---------------------------------------------------------------------------
__global__ void prep_weights(const float* __restrict__ Wq, const float* __restrict__ Wk,
                             const float* __restrict__ Wv, const float* __restrict__ We) {
    int t = blockIdx.x * blockDim.x + threadIdx.x;
    if (t >= 4 * 256 * 32) return;
    int mat = t >> 13;
    int rem = t & 8191;
    int n   = rem >> 5;
    int ku  = rem & 31;
    const float* W = mat == 0 ? Wq : mat == 1 ? Wk : mat == 2 ? Wv : We;
    uint32_t h[4], l[4];
    #pragma unroll
    for (int p = 0; p < 4; ++p) {
        float f0 = W[(ku * 8 + 2 * p) * HD + n];
        float f1 = W[(ku * 8 + 2 * p + 1) * HD + n];
        __nv_bfloat162 hh = __floats2bfloat162_rn(f0, f1);
        float l0 = f0 - __bfloat162float(hh.x);
        float l1 = f1 - __bfloat162float(hh.y);
        __nv_bfloat162 ll = __floats2bfloat162_rn(l0, l1);
        h[p] = *(uint32_t*)&hh;
        l[p] = *(uint32_t*)&ll;
    }
    *(uint4*)&g_Bth[mat][n * 256 + ku * 8] = make_uint4(h[0], h[1], h[2], h[3]);
    *(uint4*)&g_Btl[mat][n * 256 + ku * 8] = make_uint4(l[0], l[1], l[2], l[3]);
}

// ---------------------------------------------------------------------------
__device__ __forceinline__ void convert_store_A(char* smem, int buf, int tid,
                                                float4 f0, float4 f1) {
    int r = tid >> 2, u = tid & 3;
    float fv[8] = {f0.x, f0.y, f0.z, f0.w, f1.x, f1.y, f1.z, f1.w};
    uint32_t h[4], l[4];
    #pragma unroll
    for (int p = 0; p < 4; ++p) {
        __nv_bfloat162 hh = __floats2bfloat162_rn(fv[2 * p], fv[2 * p + 1]);
        float l0 = fv[2 * p] - __bfloat162float(hh.x);
        float l1 = fv[2 * p + 1] - __bfloat162float(hh.y);
        __nv_bfloat162 ll = __floats2bfloat162_rn(l0, l1);
        h[p] = *(uint32_t*)&hh;
        l[p] = *(uint32_t*)&ll;
    }
    *(uint4*)(smem + SM_A + buf * ABUF + r * 80 + u * 16)         = make_uint4(h[0], h[1], h[2], h[3]);
    *(uint4*)(smem + SM_A + buf * ABUF + 10240 + r * 80 + u * 16) = make_uint4(l[0], l[1], l[2], l[3]);
}

// ---------------------------------------------------------------------------
// GEMM mainloop: acc[2][8][4] += split-bf16( A[m0:128, :256] @ W^T )
// 512 threads, 16 warps (4 m x 4 n); warp tile 32 x 64. Double-buffered.
// ---------------------------------------------------------------------------
__device__ __forceinline__ void gemm_tile(char* smem, uint32_t sb,
                                          const float* __restrict__ A, int m0,
                                          int mat, int tid, float acc[2][8][4]) {
    int lane = tid & 31, w = tid >> 5;
    int warp_m = w & 3, warp_n = w >> 2;
    int qrow = lane >> 2, qcol = lane & 3;
    const __nv_bfloat16* Bh = g_Bth[mat];
    const __nv_bfloat16* Bl = g_Btl[mat];
    int r = tid >> 2, u = tid & 3;

    // prologue: chunk 0
    {
        const float4* src = (const float4*)(A + (size_t)(m0 + r) * DIN + u * 8);
        float4 f0 = src[0], f1 = src[1];
        #pragma unroll
        for (int i = 0; i < 2; ++i) {
            int un = tid + 512 * i;
            int n = un >> 2, uu = un & 3;
            cp_async16(sb + SM_B + n * 80 + uu * 16,         &Bh[n * 256 + uu * 8]);
            cp_async16(sb + SM_B + 20480 + n * 80 + uu * 16, &Bl[n * 256 + uu * 8]);
        }
        CP_COMMIT;
        convert_store_A(smem, 0, tid, f0, f1);
        CP_WAIT0;
        __syncthreads();
    }

    for (int kc = 0; kc < 8; ++kc) {
        int cur = kc & 1, nxt = cur ^ 1;
        float4 f0, f1;
        if (kc < 7) {
            const float4* src = (const float4*)(A + (size_t)(m0 + r) * DIN + (kc + 1) * 32 + u * 8);
            f0 = src[0]; f1 = src[1];
            #pragma unroll
            for (int i = 0; i < 2; ++i) {
                int un = tid + 512 * i;
                int n = un >> 2, uu = un & 3;
                cp_async16(sb + SM_B + nxt * BBUF + n * 80 + uu * 16,
                           &Bh[n * 256 + (kc + 1) * 32 + uu * 8]);
                cp_async16(sb + SM_B + nxt * BBUF + 20480 + n * 80 + uu * 16,
                           &Bl[n * 256 + (kc + 1) * 32 + uu * 8]);
            }
            CP_COMMIT;
        }

        char* Ab = smem + SM_A + cur * ABUF;
        char* Bb = smem + SM_B + cur * BBUF;
        #pragma unroll
        for (int ks = 0; ks < 2; ++ks) {
            uint32_t ah[2][4], al[2][4];
            #pragma unroll
            for (int mf = 0; mf < 2; ++mf) {
                int base = (warp_m * 32 + mf * 16 + qrow) * 80 + qcol * 4 + ks * 32;
                ah[mf][0] = *(const uint32_t*)(Ab + base);
                ah[mf][1] = *(const uint32_t*)(Ab + base + 640);
                ah[mf][2] = *(const uint32_t*)(Ab + base + 16);
                ah[mf][3] = *(const uint32_t*)(Ab + base + 656);
                al[mf][0] = *(const uint32_t*)(Ab + 10240 + base);
                al[mf][1] = *(const uint32_t*)(Ab + 10240 + base + 640);
                al[mf][2] = *(const uint32_t*)(Ab + 10240 + base + 16);
                al[mf][3] = *(const uint32_t*)(Ab + 10240 + base + 656);
            }
            #pragma unroll
            for (int nf = 0; nf < 8; ++nf) {
                int nb = (warp_n * 64 + nf * 8 + qrow) * 80 + qcol * 4 + ks * 32;
                uint32_t bh[2], bl[2];
                bh[0] = *(const uint32_t*)(Bb + nb);
                bh[1] = *(const uint32_t*)(Bb + nb + 16);
                bl[0] = *(const uint32_t*)(Bb + 20480 + nb);
                bl[1] = *(const uint32_t*)(Bb + 20480 + nb + 16);
                #pragma unroll
                for (int mf = 0; mf < 2; ++mf) {
                    mma16816(acc[mf][nf], ah[mf], bh);
                    mma16816(acc[mf][nf], al[mf], bh);
                    mma16816(acc[mf][nf], ah[mf], bl);
                }
            }
        }

        if (kc < 7) {
            convert_store_A(smem, nxt, tid, f0, f1);
            CP_WAIT0;
            __syncthreads();
        }
    }
}

// ---------------------------------------------------------------------------
// QKV GEMM. grid (125, 3), 512 threads.
// ---------------------------------------------------------------------------
__global__ __launch_bounds__(512, 1) void qkv_mm(const float* __restrict__ x) {
    extern __shared__ char smem[];
    uint32_t sb = smem_u32(smem);
    int tid = threadIdx.x;
    int m0 = blockIdx.x * 128;
    int mat = blockIdx.y;

    float acc[2][8][4];
    #pragma unroll
    for (int mf = 0; mf < 2; ++mf)
        #pragma unroll
        for (int nf = 0; nf < 8; ++nf)
            #pragma unroll
            for (int p = 0; p < 4; ++p) acc[mf][nf][p] = 0.0f;

    gemm_tile(smem, sb, x, m0, mat, tid, acc);

    int lane = tid & 31, w = tid >> 5;
    int warp_m = w & 3, warp_n = w >> 2;
    int qrow = lane >> 2, qcol = lane & 3;
    float* out = mat == 0 ? g_q : mat == 1 ? g_k : g_v;

    #pragma unroll
    for (int mf = 0; mf < 2; ++mf) {
        int r0 = m0 + warp_m * 32 + mf * 16 + qrow;
        #pragma unroll
        for (int nf = 0; nf < 8; ++nf) {
            int c = warp_n * 64 + nf * 8 + qcol * 2;
            *(float2*)(out + (size_t)r0 * HD + c)       = make_float2(acc[mf][nf][0], acc[mf][nf][1]);
            *(float2*)(out + (size_t)(r0 + 8) * HD + c) = make_float2(acc[mf][nf][2], acc[mf][nf][3]);
        }
    }
}

// ---------------------------------------------------------------------------
// Edge GEMM + fused attention epilogue. grid 2000, 512 threads.
// ---------------------------------------------------------------------------
__global__ __launch_bounds__(512, 1) void edge_mm(const float* __restrict__ edge_attr,
                                                  const int* __restrict__ ei,
                                                  const float* __restrict__ coords,
                                                  const float* __restrict__ We,
                                                  float* __restrict__ eout) {
    extern __shared__ char smem[];
    uint32_t sb = smem_u32(smem);
    int tid = threadIdx.x;
    int m0 = blockIdx.x * 128;

    int*   sSrc = (int*)(smem + SM_SRC);
    int*   sDst = (int*)(smem + SM_DST);
    float* sDist = (float*)(smem + SM_DIST);
    float* sAx  = (float*)(smem + SM_AX);

    if (tid < 128) {
        int s = ei[m0 + tid];
        int d = ei[NEDGES + m0 + tid];
        sSrc[tid] = s; sDst[tid] = d;
        float dx = coords[3 * s + 0] - coords[3 * d + 0];
        float dy = coords[3 * s + 1] - coords[3 * d + 1];
        float dz = coords[3 * s + 2] - coords[3 * d + 2];
        sDist[tid] = 0.1f * sqrtf(dx * dx + dy * dy + dz * dz);
    }
    __syncthreads();

    float acc[2][8][4];
    #pragma unroll
    for (int mf = 0; mf < 2; ++mf)
        #pragma unroll
        for (int nf = 0; nf < 8; ++nf)
            #pragma unroll
            for (int p = 0; p < 4; ++p) acc[mf][nf][p] = 0.0f;

    gemm_tile(smem, sb, edge_attr, m0, 3, tid, acc);

    int lane = tid & 31, w = tid >> 5;
    int warp_m = w & 3, warp_n = w >> 2;
    int qrow = lane >> 2, qcol = lane & 3;
    const float invs = 0.17677669529663687f;   // 1/sqrt(32)

    #pragma unroll
    for (int mf = 0; mf < 2; ++mf) {
        int erow0 = warp_m * 32 + mf * 16 + qrow;
        #pragma unroll
        for (int half = 0; half < 2; ++half) {
            int e = erow0 + 8 * half;
            int src = sSrc[e], dst = sDst[e];
            float de = sDist[e];
            float hsum0 = 0.0f, hsum1 = 0.0f;
            #pragma unroll
            for (int nf = 0; nf < 8; ++nf) {
                int c = warp_n * 64 + nf * 8 + qcol * 2;
                float2 kk = *(const float2*)(g_k + (size_t)src * HD + c);
                float2 qq = *(const float2*)(g_q + (size_t)dst * HD + c);
                float2 wl = *(const float2*)(We + (size_t)DIN * HD + c);
                float d0 = acc[mf][nf][2 * half + 0];
                float d1 = acc[mf][nf][2 * half + 1];
                float s0 = fminf(5.0f, fmaxf(-5.0f, kk.x * qq.x * invs));
                float s1 = fminf(5.0f, fmaxf(-5.0f, kk.y * qq.y * invs));
                float a0 = s0 * (d0 + de * wl.x);
                float a1 = s1 * (d1 + de * wl.y);
                *(float2*)(eout + (size_t)(m0 + e) * HD + c) = make_float2(a0, a1);
                if (nf < 4) hsum0 += a0 + a1; else hsum1 += a0 + a1;
            }
            hsum0 += __shfl_xor_sync(0xffffffffu, hsum0, 1);
            hsum0 += __shfl_xor_sync(0xffffffffu, hsum0, 2);
            hsum1 += __shfl_xor_sync(0xffffffffu, hsum1, 1);
            hsum1 += __shfl_xor_sync(0xffffffffu, hsum1, 2);
            if (qcol == 0) {
                float ax0 = expf(fminf(5.0f, fmaxf(-5.0f, hsum0)));
                float ax1 = expf(fminf(5.0f, fmaxf(-5.0f, hsum1)));
                int h0 = 2 * warp_n, h1 = h0 + 1;
                sAx[e * NH + h0] = ax0;
                sAx[e * NH + h1] = ax1;
                atomicAdd(&g_z[(size_t)dst * NH + h0], ax0);
                atomicAdd(&g_z[(size_t)dst * NH + h1], ax1);
            }
        }
    }
    __syncthreads();

    // scatter wV += v[src] * ax : 1024 (edge, head) pairs over 512 threads
    #pragma unroll
    for (int i = 0; i < 2; ++i) {
        int p = tid + 512 * i;
        int e = p >> 3, h = p & 7;
        int src = sSrc[e], dst = sDst[e];
        float ax = sAx[e * NH + h];
        const float4* v4 = (const float4*)(g_v + (size_t)src * HD + h * 32);
        float* wv = g_wV + (size_t)dst * HD + h * 32;
        #pragma unroll
        for (int j = 0; j < 8; ++j) {
            float4 vv = v4[j];
            atomicAdd(wv + 4 * j + 0, vv.x * ax);
            atomicAdd(wv + 4 * j + 1, vv.y * ax);
            atomicAdd(wv + 4 * j + 2, vv.z * ax);
            atomicAdd(wv + 4 * j + 3, vv.w * ax);
        }
    }
}

// ---------------------------------------------------------------------------
__global__ void finalize_kernel(float* __restrict__ hout) {
    int i = blockIdx.x * blockDim.x + threadIdx.x;
    if (i < NNODES * HD) {
        int n = i >> 8;
        int h = (i & 255) >> 5;
        hout[i] = g_wV[i] / (g_z[n * NH + h] + 1e-6f);
    }
}

// ---------------------------------------------------------------------------
extern "C" void kernel_launch(void* const* d_in, const int* in_sizes, int n_in,
                              void* d_out, int out_size)
{
    const float* x         = (const float*)d_in[0];
    const float* edge_attr = (const float*)d_in[1];
    const int*   ei        = (const int*)d_in[2];
    const float* coords    = (const float*)d_in[3];
    const float* Wq        = (const float*)d_in[4];
    const float* Wk        = (const float*)d_in[5];
    const float* Wv        = (const float*)d_in[6];
    const float* We        = (const float*)d_in[7];

    float* out  = (float*)d_out;
    float* hout = out;
    float* eout = out + (size_t)NNODES * HD;
    float* cout = eout + (size_t)NEDGES * HD;

    static bool attr_set = false;
    if (!attr_set) {
        cudaFuncSetAttribute(qkv_mm,  cudaFuncAttributeMaxDynamicSharedMemorySize, SM_TOTAL);
        cudaFuncSetAttribute(edge_mm, cudaFuncAttributeMaxDynamicSharedMemorySize, SM_TOTAL);
        attr_set = true;
    }

    zero_kernel<<<(NNODES * HD + 255) / 256, 256>>>(coords, cout);
    prep_weights<<<128, 256>>>(Wq, Wk, Wv, We);
    qkv_mm<<<dim3(125, 3), 512, SM_TOTAL>>>(x);
    edge_mm<<<2000, 512, SM_TOTAL>>>(edge_attr, ei, coords, We, eout);
    finalize_kernel<<<(NNODES * HD + 255) / 256, 256>>>(hout);
}

// round 7
// speedup vs baseline: 1.8856x; 1.0329x over previous
#include <cuda_runtime.h>
#include <cuda_bf16.h>
#include <math.h>
#include <stdint.h>

#define NNODES 16000
#define DIN    256
#define HD     256
#define NH     8
#define NEDGES 256000

// ---------------- device scratch ----------------
__device__ float g_q[NNODES * HD];
__device__ float g_k[NNODES * HD];
__device__ float g_v[NNODES * HD];
__device__ float g_wV[NNODES * HD];
__device__ float g_z[NNODES * NH];
// transposed bf16 weight images: [mat][n=256][k=256]; mat: 0=Wq 1=Wk 2=Wv 3=We
__device__ __nv_bfloat16 g_Bth[4][256 * 256];
__device__ __nv_bfloat16 g_Btl[4][256 * 256];

// ---------------- helpers ----------------
__device__ __forceinline__ void mma16816(float* d, const uint32_t* a, const uint32_t* b) {
    asm volatile(
        "mma.sync.aligned.m16n8k16.row.col.f32.bf16.bf16.f32 "
        "{%0,%1,%2,%3}, {%4,%5,%6,%7}, {%8,%9}, {%0,%1,%2,%3};"
        : "+f"(d[0]), "+f"(d[1]), "+f"(d[2]), "+f"(d[3])
        : "r"(a[0]), "r"(a[1]), "r"(a[2]), "r"(a[3]), "r"(b[0]), "r"(b[1]));
}
__device__ __forceinline__ uint32_t smem_u32(const void* p) {
    uint32_t a;
    asm("{ .reg .u64 t; cvta.to.shared.u64 t, %1; cvt.u32.u64 %0, t; }" : "=r"(a) : "l"(p));
    return a;
}
__device__ __forceinline__ void cp_async16(uint32_t dst, const void* src) {
    asm volatile("cp.async.cg.shared.global [%0], [%1], 16;" :: "r"(dst), "l"(src));
}
#define CP_COMMIT asm volatile("cp.async.commit_group;" ::: "memory")
#define CP_WAIT0  asm volatile("cp.async.wait_group 0;" ::: "memory")
#define LDSM4(r, addr) \
    asm volatile("ldmatrix.sync.aligned.m8n8.x4.shared.b16 {%0,%1,%2,%3}, [%4];" \
        : "=r"((r)[0]), "=r"((r)[1]), "=r"((r)[2]), "=r"((r)[3]) : "r"(addr))

// SMEM layout (bytes). A/B tiles use 80B rows (conflict-free fragment/ldsm LDS).
#define SM_SRC   0
#define SM_DST   512
#define SM_DIST  1024
#define SM_AX    1536      // 128*8 floats = 4096
#define SM_A     5632      // 2 bufs x (hi 10240 + lo 10240)
#define ABUF     20480
#define SM_B     46592     // 2 bufs x (hi 20480 + lo 20480)
#define BBUF     40960
#define SM_TOTAL 128512

// ---------------------------------------------------------------------------
__global__ void zero_kernel(const float* __restrict__ coords, float* __restrict__ cout) {
    int i = blockIdx.x * blockDim.x + threadIdx.x;
    if (i < NNODES * HD) g_wV[i] = 0.0f;
    if (i < NNODES * NH) g_z[i] = 0.0f;
    if (i < NNODES * 3)  cout[i] = coords[i];
}

// ---------------------------------------------------------------------------
// Weight prep: W[k][n] fp32 -> g_Bt{h,l}[mat][n][k] bf16 (hi/lo split).
// ---------------------------------------------------------------------------
__global__ void prep_weights(const float* __restrict__ Wq, const float* __restrict__ Wk,
                             const float* __restrict__ Wv, const float* __restrict__ We) {
    int t = blockIdx.x * blockDim.x + threadIdx.x;
    if (t >= 4 * 256 * 32) return;
    int mat = t >> 13;
    int rem = t & 8191;
    int n   = rem >> 5;
    int ku  = rem & 31;
    const float* W = mat == 0 ? Wq : mat == 1 ? Wk : mat == 2 ? Wv : We;
    uint32_t h[4], l[4];
    #pragma unroll
    for (int p = 0; p < 4; ++p) {
        float f0 = W[(ku * 8 + 2 * p) * HD + n];
        float f1 = W[(ku * 8 + 2 * p + 1) * HD + n];
        __nv_bfloat162 hh = __floats2bfloat162_rn(f0, f1);
        float l0 = f0 - __bfloat162float(hh.x);
        float l1 = f1 - __bfloat162float(hh.y);
        __nv_bfloat162 ll = __floats2bfloat162_rn(l0, l1);
        h[p] = *(uint32_t*)&hh;
        l[p] = *(uint32_t*)&ll;
    }
    *(uint4*)&g_Bth[mat][n * 256 + ku * 8] = make_uint4(h[0], h[1], h[2], h[3]);
    *(uint4*)&g_Btl[mat][n * 256 + ku * 8] = make_uint4(l[0], l[1], l[2], l[3]);
}

// ---------------------------------------------------------------------------
__device__ __forceinline__ void convert_store_A(char* smem, int buf, int tid,
                                                float4 f0, float4 f1) {
    int r = tid >> 2, u = tid & 3;
    float fv[8] = {f0.x, f0.y, f0.z, f0.w, f1.x, f1.y, f1.z, f1.w};
    uint32_t h[4], l[4];
    #pragma unroll
    for (int p = 0; p < 4; ++p) {
        __nv_bfloat162 hh = __floats2bfloat162_rn(fv[2 * p], fv[2 * p + 1]);
        float l0 = fv[2 * p] - __bfloat162float(hh.x);
        float l1 = fv[2 * p + 1] - __bfloat162float(hh.y);
        __nv_bfloat162 ll = __floats2bfloat162_rn(l0, l1);
        h[p] = *(uint32_t*)&hh;
        l[p] = *(uint32_t*)&ll;
    }
    *(uint4*)(smem + SM_A + buf * ABUF + r * 80 + u * 16)         = make_uint4(h[0], h[1], h[2], h[3]);
    *(uint4*)(smem + SM_A + buf * ABUF + 10240 + r * 80 + u * 16) = make_uint4(l[0], l[1], l[2], l[3]);
}

// ---------------------------------------------------------------------------
// GEMM mainloop: acc[2][8][4] += split-bf16( A[m0:128, :256] @ W^T )
// 512 threads, 16 warps (4 m x 4 n); warp tile 32 x 64. Double-buffered,
// ldmatrix.x4 fragment loads.
// ---------------------------------------------------------------------------
__device__ __forceinline__ void gemm_tile(char* smem, uint32_t sb,
                                          const float* __restrict__ A, int m0,
                                          int mat, int tid, float acc[2][8][4]) {
    int lane = tid & 31, w = tid >> 5;
    int warp_m = w & 3, warp_n = w >> 2;
    const __nv_bfloat16* Bh = g_Bth[mat];
    const __nv_bfloat16* Bl = g_Btl[mat];
    int r = tid >> 2, u = tid & 3;

    // ldmatrix per-lane row addresses (offsets within a buffer)
    // A: matrices {m0-7 k0-7, m8-15 k0-7, m0-7 k8-15, m8-15 k8-15}
    uint32_t aRow = (uint32_t)(warp_m * 32 + (lane & 7) + ((lane >> 3) & 1) * 8);
    uint32_t aOff = aRow * 80 + ((lane >> 4) & 1) * 16;
    // B: matrices {n0-7 k0-7, n0-7 k8-15, n8-15 k0-7, n8-15 k8-15}
    uint32_t bRow = (uint32_t)(warp_n * 64 + (lane & 7) + ((lane >> 4) & 1) * 8);
    uint32_t bOff = bRow * 80 + ((lane >> 3) & 1) * 16;

    // prologue: chunk 0
    {
        const float4* src = (const float4*)(A + (size_t)(m0 + r) * DIN + u * 8);
        float4 f0 = src[0], f1 = src[1];
        #pragma unroll
        for (int i = 0; i < 2; ++i) {
            int un = tid + 512 * i;
            int n = un >> 2, uu = un & 3;
            cp_async16(sb + SM_B + n * 80 + uu * 16,         &Bh[n * 256 + uu * 8]);
            cp_async16(sb + SM_B + 20480 + n * 80 + uu * 16, &Bl[n * 256 + uu * 8]);
        }
        CP_COMMIT;
        convert_store_A(smem, 0, tid, f0, f1);
        CP_WAIT0;
        __syncthreads();
    }

    for (int kc = 0; kc < 8; ++kc) {
        int cur = kc & 1, nxt = cur ^ 1;
        float4 f0, f1;
        if (kc < 7) {
            const float4* src = (const float4*)(A + (size_t)(m0 + r) * DIN + (kc + 1) * 32 + u * 8);
            f0 = src[0]; f1 = src[1];
            #pragma unroll
            for (int i = 0; i < 2; ++i) {
                int un = tid + 512 * i;
                int n = un >> 2, uu = un & 3;
                cp_async16(sb + SM_B + nxt * BBUF + n * 80 + uu * 16,
                           &Bh[n * 256 + (kc + 1) * 32 + uu * 8]);
                cp_async16(sb + SM_B + nxt * BBUF + 20480 + n * 80 + uu * 16,
                           &Bl[n * 256 + (kc + 1) * 32 + uu * 8]);
            }
            CP_COMMIT;
        }

        uint32_t aBase = sb + SM_A + cur * ABUF + aOff;
        uint32_t bBase = sb + SM_B + cur * BBUF + bOff;
        #pragma unroll
        for (int ks = 0; ks < 2; ++ks) {
            uint32_t ah[2][4], al[2][4];
            LDSM4(ah[0], aBase + ks * 32);
            LDSM4(ah[1], aBase + ks * 32 + 1280);           // +16 rows
            LDSM4(al[0], aBase + ks * 32 + 10240);
            LDSM4(al[1], aBase + ks * 32 + 10240 + 1280);
            uint32_t bh[4][4], bl[4][4];
            #pragma unroll
            for (int pr = 0; pr < 4; ++pr) {
                LDSM4(bh[pr], bBase + ks * 32 + pr * 1280);          // +16 n-rows per pair
                LDSM4(bl[pr], bBase + ks * 32 + pr * 1280 + 20480);
            }
            #pragma unroll
            for (int pr = 0; pr < 4; ++pr) {
                #pragma unroll
                for (int sub = 0; sub < 2; ++sub) {
                    int nf = pr * 2 + sub;
                    uint32_t b2h[2] = {bh[pr][2 * sub], bh[pr][2 * sub + 1]};
                    uint32_t b2l[2] = {bl[pr][2 * sub], bl[pr][2 * sub + 1]};
                    #pragma unroll
                    for (int mf = 0; mf < 2; ++mf) {
                        mma16816(acc[mf][nf], ah[mf], b2h);
                        mma16816(acc[mf][nf], al[mf], b2h);
                        mma16816(acc[mf][nf], ah[mf], b2l);
                    }
                }
            }
        }

        if (kc < 7) {
            convert_store_A(smem, nxt, tid, f0, f1);
            CP_WAIT0;
            __syncthreads();
        }
    }
}

// ---------------------------------------------------------------------------
// QKV GEMM. grid (125, 3), 512 threads.
// ---------------------------------------------------------------------------
__global__ __launch_bounds__(512, 1) void qkv_mm(const float* __restrict__ x) {
    extern __shared__ char smem[];
    uint32_t sb = smem_u32(smem);
    int tid = threadIdx.x;
    int m0 = blockIdx.x * 128;
    int mat = blockIdx.y;

    float acc[2][8][4];
    #pragma unroll
    for (int mf = 0; mf < 2; ++mf)
        #pragma unroll
        for (int nf = 0; nf < 8; ++nf)
            #pragma unroll
            for (int p = 0; p < 4; ++p) acc[mf][nf][p] = 0.0f;

    gemm_tile(smem, sb, x, m0, mat, tid, acc);

    int lane = tid & 31, w = tid >> 5;
    int warp_m = w & 3, warp_n = w >> 2;
    int qrow = lane >> 2, qcol = lane & 3;
    float* out = mat == 0 ? g_q : mat == 1 ? g_k : g_v;

    #pragma unroll
    for (int mf = 0; mf < 2; ++mf) {
        int r0 = m0 + warp_m * 32 + mf * 16 + qrow;
        #pragma unroll
        for (int nf = 0; nf < 8; ++nf) {
            int c = warp_n * 64 + nf * 8 + qcol * 2;
            *(float2*)(out + (size_t)r0 * HD + c)       = make_float2(acc[mf][nf][0], acc[mf][nf][1]);
            *(float2*)(out + (size_t)(r0 + 8) * HD + c) = make_float2(acc[mf][nf][2], acc[mf][nf][3]);
        }
    }
}

// ---------------------------------------------------------------------------
// Edge GEMM + fused attention epilogue. grid 2000, 512 threads.
// ---------------------------------------------------------------------------
__global__ __launch_bounds__(512, 1) void edge_mm(const float* __restrict__ edge_attr,
                                                  const int* __restrict__ ei,
                                                  const float* __restrict__ coords,
                                                  const float* __restrict__ We,
                                                  float* __restrict__ eout) {
    extern __shared__ char smem[];
    uint32_t sb = smem_u32(smem);
    int tid = threadIdx.x;
    int m0 = blockIdx.x * 128;

    int*   sSrc = (int*)(smem + SM_SRC);
    int*   sDst = (int*)(smem + SM_DST);
    float* sDist = (float*)(smem + SM_DIST);
    float* sAx  = (float*)(smem + SM_AX);

    if (tid < 128) {
        int s = ei[m0 + tid];
        int d = ei[NEDGES + m0 + tid];
        sSrc[tid] = s; sDst[tid] = d;
        float dx = coords[3 * s + 0] - coords[3 * d + 0];
        float dy = coords[3 * s + 1] - coords[3 * d + 1];
        float dz = coords[3 * s + 2] - coords[3 * d + 2];
        sDist[tid] = 0.1f * sqrtf(dx * dx + dy * dy + dz * dz);
    }
    __syncthreads();

    float acc[2][8][4];
    #pragma unroll
    for (int mf = 0; mf < 2; ++mf)
        #pragma unroll
        for (int nf = 0; nf < 8; ++nf)
            #pragma unroll
            for (int p = 0; p < 4; ++p) acc[mf][nf][p] = 0.0f;

    gemm_tile(smem, sb, edge_attr, m0, 3, tid, acc);

    int lane = tid & 31, w = tid >> 5;
    int warp_m = w & 3, warp_n = w >> 2;
    int qrow = lane >> 2, qcol = lane & 3;
    const float invs = 0.17677669529663687f;   // 1/sqrt(32)

    #pragma unroll
    for (int mf = 0; mf < 2; ++mf) {
        int erow0 = warp_m * 32 + mf * 16 + qrow;
        #pragma unroll
        for (int half = 0; half < 2; ++half) {
            int e = erow0 + 8 * half;
            int src = sSrc[e], dst = sDst[e];
            float de = sDist[e];
            float hsum0 = 0.0f, hsum1 = 0.0f;
            #pragma unroll
            for (int nf = 0; nf < 8; ++nf) {
                int c = warp_n * 64 + nf * 8 + qcol * 2;
                float2 kk = *(const float2*)(g_k + (size_t)src * HD + c);
                float2 qq = *(const float2*)(g_q + (size_t)dst * HD + c);
                float2 wl = *(const float2*)(We + (size_t)DIN * HD + c);
                float d0 = acc[mf][nf][2 * half + 0];
                float d1 = acc[mf][nf][2 * half + 1];
                float s0 = fminf(5.0f, fmaxf(-5.0f, kk.x * qq.x * invs));
                float s1 = fminf(5.0f, fmaxf(-5.0f, kk.y * qq.y * invs));
                float a0 = s0 * (d0 + de * wl.x);
                float a1 = s1 * (d1 + de * wl.y);
                *(float2*)(eout + (size_t)(m0 + e) * HD + c) = make_float2(a0, a1);
                if (nf < 4) hsum0 += a0 + a1; else hsum1 += a0 + a1;
            }
            hsum0 += __shfl_xor_sync(0xffffffffu, hsum0, 1);
            hsum0 += __shfl_xor_sync(0xffffffffu, hsum0, 2);
            hsum1 += __shfl_xor_sync(0xffffffffu, hsum1, 1);
            hsum1 += __shfl_xor_sync(0xffffffffu, hsum1, 2);
            if (qcol == 0) {
                float ax0 = expf(fminf(5.0f, fmaxf(-5.0f, hsum0)));
                float ax1 = expf(fminf(5.0f, fmaxf(-5.0f, hsum1)));
                int h0 = 2 * warp_n, h1 = h0 + 1;
                sAx[e * NH + h0] = ax0;
                sAx[e * NH + h1] = ax1;
                atomicAdd(&g_z[(size_t)dst * NH + h0], ax0);
                atomicAdd(&g_z[(size_t)dst * NH + h1], ax1);
            }
        }
    }
    __syncthreads();

    // scatter wV += v[src] * ax : 1024 (edge, head) pairs over 512 threads
    #pragma unroll
    for (int i = 0; i < 2; ++i) {
        int p = tid + 512 * i;
        int e = p >> 3, h = p & 7;
        int src = sSrc[e], dst = sDst[e];
        float ax = sAx[e * NH + h];
        const float4* v4 = (const float4*)(g_v + (size_t)src * HD + h * 32);
        float* wv = g_wV + (size_t)dst * HD + h * 32;
        #pragma unroll
        for (int j = 0; j < 8; ++j) {
            float4 vv = v4[j];
            atomicAdd(wv + 4 * j + 0, vv.x * ax);
            atomicAdd(wv + 4 * j + 1, vv.y * ax);
            atomicAdd(wv + 4 * j + 2, vv.z * ax);
            atomicAdd(wv + 4 * j + 3, vv.w * ax);
        }
    }
}

// ---------------------------------------------------------------------------
__global__ void finalize_kernel(float* __restrict__ hout) {
    int i = blockIdx.x * blockDim.x + threadIdx.x;
    if (i < NNODES * HD) {
        int n = i >> 8;
        int h = (i & 255) >> 5;
        hout[i] = g_wV[i] / (g_z[n * NH + h] + 1e-6f);
    }
}

// ---------------------------------------------------------------------------
extern "C" void kernel_launch(void* const* d_in, const int* in_sizes, int n_in,
                              void* d_out, int out_size)
{
    const float* x         = (const float*)d_in[0];
    const float* edge_attr = (const float*)d_in[1];
    const int*   ei        = (const int*)d_in[2];
    const float* coords    = (const float*)d_in[3];
    const float* Wq        = (const float*)d_in[4];
    const float* Wk        = (const float*)d_in[5];
    const float* Wv        = (const float*)d_in[6];
    const float* We        = (const float*)d_in[7];

    float* out  = (float*)d_out;
    float* hout = out;
    float* eout = out + (size_t)NNODES * HD;
    float* cout = eout + (size_t)NEDGES * HD;

    static bool attr_set = false;
    if (!attr_set) {
        cudaFuncSetAttribute(qkv_mm,  cudaFuncAttributeMaxDynamicSharedMemorySize, SM_TOTAL);
        cudaFuncSetAttribute(edge_mm, cudaFuncAttributeMaxDynamicSharedMemorySize, SM_TOTAL);
        attr_set = true;
    }

    zero_kernel<<<(NNODES * HD + 255) / 256, 256>>>(coords, cout);
    prep_weights<<<128, 256>>>(Wq, Wk, Wv, We);
    qkv_mm<<<dim3(125, 3), 512, SM_TOTAL>>>(x);
    edge_mm<<<2000, 512, SM_TOTAL>>>(edge_attr, ei, coords, We, eout);
    finalize_kernel<<<(NNODES * HD + 255) / 256, 256>>>(hout);
}

// round 8
// speedup vs baseline: 1.9551x; 1.0369x over previous
#include <cuda_runtime.h>
#include <cuda_bf16.h>
#include <math.h>
#include <stdint.h>

#define NNODES 16000
#define DIN    256
#define HD     256
#define NH     8
#define NEDGES 256000

// ---------------- device scratch ----------------
__device__ float g_q[NNODES * HD];
__device__ float g_k[NNODES * HD];
__device__ float g_v[NNODES * HD];
__device__ float g_wV[NNODES * HD];
__device__ float g_z[NNODES * NH];
// transposed bf16 weight images: [mat][n=256][k=256]; mat: 0=Wq 1=Wk 2=Wv 3=We
__device__ __nv_bfloat16 g_Bth[4][256 * 256];
__device__ __nv_bfloat16 g_Btl[4][256 * 256];

// ---------------- helpers ----------------
__device__ __forceinline__ void mma16816(float* d, const uint32_t* a, const uint32_t* b) {
    asm volatile(
        "mma.sync.aligned.m16n8k16.row.col.f32.bf16.bf16.f32 "
        "{%0,%1,%2,%3}, {%4,%5,%6,%7}, {%8,%9}, {%0,%1,%2,%3};"
        : "+f"(d[0]), "+f"(d[1]), "+f"(d[2]), "+f"(d[3])
        : "r"(a[0]), "r"(a[1]), "r"(a[2]), "r"(a[3]), "r"(b[0]), "r"(b[1]));
}
__device__ __forceinline__ uint32_t smem_u32(const void* p) {
    uint32_t a;
    asm("{ .reg .u64 t; cvta.to.shared.u64 t, %1; cvt.u32.u64 %0, t; }" : "=r"(a) : "l"(p));
    return a;
}
__device__ __forceinline__ void cp_async16(uint32_t dst, const void* src) {
    asm volatile("cp.async.cg.shared.global [%0], [%1], 16;" :: "r"(dst), "l"(src));
}
#define CP_COMMIT asm volatile("cp.async.commit_group;" ::: "memory")
#define CP_WAIT0  asm volatile("cp.async.wait_group 0;" ::: "memory")
#define LDSM4(r, addr) \
    asm volatile("ldmatrix.sync.aligned.m8n8.x4.shared.b16 {%0,%1,%2,%3}, [%4];" \
        : "=r"((r)[0]), "=r"((r)[1]), "=r"((r)[2]), "=r"((r)[3]) : "r"(addr))

// SMEM layout (bytes). A/B tiles use 80B rows (conflict-free ldsm).
// A: 128 rows x 32 k (hi 10240 + lo 10240) x 2 bufs
// B: 128 n   x 32 k (hi 10240 + lo 10240) x 2 bufs
#define SM_SRC   0
#define SM_DST   512
#define SM_DIST  1024
#define SM_AX    1536      // 128*4 floats = 2048
#define SM_A     3584
#define ABUF     20480
#define SM_B     44544
#define BBUF     20480
#define SM_TOTAL 85504

// ---------------------------------------------------------------------------
__global__ void zero_kernel(const float* __restrict__ coords, float* __restrict__ cout) {
    int i = blockIdx.x * blockDim.x + threadIdx.x;
    if (i < NNODES * HD) g_wV[i] = 0.0f;
    if (i < NNODES * NH) g_z[i] = 0.0f;
    if (i < NNODES * 3)  cout[i] = coords[i];
}

// ---------------------------------------------------------------------------
// Weight prep: W[k][n] fp32 -> g_Bt{h,l}[mat][n][k] bf16 (hi/lo split).
// ---------------------------------------------------------------------------
__global__ void prep_weights(const float* __restrict__ Wq, const float* __restrict__ Wk,
                             const float* __restrict__ Wv, const float* __restrict__ We) {
    int t = blockIdx.x * blockDim.x + threadIdx.x;
    if (t >= 4 * 256 * 32) return;
    int mat = t >> 13;
    int rem = t & 8191;
    int n   = rem >> 5;
    int ku  = rem & 31;
    const float* W = mat == 0 ? Wq : mat == 1 ? Wk : mat == 2 ? Wv : We;
    uint32_t h[4], l[4];
    #pragma unroll
    for (int p = 0; p < 4; ++p) {
        float f0 = W[(ku * 8 + 2 * p) * HD + n];
        float f1 = W[(ku * 8 + 2 * p + 1) * HD + n];
        __nv_bfloat162 hh = __floats2bfloat162_rn(f0, f1);
        float l0 = f0 - __bfloat162float(hh.x);
        float l1 = f1 - __bfloat162float(hh.y);
        __nv_bfloat162 ll = __floats2bfloat162_rn(l0, l1);
        h[p] = *(uint32_t*)&hh;
        l[p] = *(uint32_t*)&ll;
    }
    *(uint4*)&g_Bth[mat][n * 256 + ku * 8] = make_uint4(h[0], h[1], h[2], h[3]);
    *(uint4*)&g_Btl[mat][n * 256 + ku * 8] = make_uint4(l[0], l[1], l[2], l[3]);
}

// ---------------------------------------------------------------------------
// A convert+store: 256 threads, each handles 16 k-floats of one row.
// f[4] = 16 consecutive floats at (row = tid>>1, k = (tid&1)*16).
// ---------------------------------------------------------------------------
__device__ __forceinline__ void convert_store_A(char* smem, int buf, int tid,
                                                const float4* f) {
    int r = tid >> 1, u = tid & 1;
    const float* fv = (const float*)f;
    uint32_t h[8], l[8];
    #pragma unroll
    for (int p = 0; p < 8; ++p) {
        __nv_bfloat162 hh = __floats2bfloat162_rn(fv[2 * p], fv[2 * p + 1]);
        float l0 = fv[2 * p] - __bfloat162float(hh.x);
        float l1 = fv[2 * p + 1] - __bfloat162float(hh.y);
        __nv_bfloat162 ll = __floats2bfloat162_rn(l0, l1);
        h[p] = *(uint32_t*)&hh;
        l[p] = *(uint32_t*)&ll;
    }
    char* base = smem + SM_A + buf * ABUF + r * 80 + u * 32;
    *(uint4*)(base)              = make_uint4(h[0], h[1], h[2], h[3]);
    *(uint4*)(base + 16)         = make_uint4(h[4], h[5], h[6], h[7]);
    *(uint4*)(base + 10240)      = make_uint4(l[0], l[1], l[2], l[3]);
    *(uint4*)(base + 10240 + 16) = make_uint4(l[4], l[5], l[6], l[7]);
}

// ---------------------------------------------------------------------------
// GEMM mainloop: acc[2][8][4] += split-bf16( A[m0:128, :256] @ W[n0:128]^T )
// 256 threads, 8 warps (4 m x 2 n); warp tile 32 x 64. Double-buffered.
// ---------------------------------------------------------------------------
__device__ __forceinline__ void gemm_tile(char* smem, uint32_t sb,
                                          const float* __restrict__ A, int m0,
                                          int mat, int n0, int tid, float acc[2][8][4]) {
    int lane = tid & 31, w = tid >> 5;
    int warp_m = w & 3, warp_n = w >> 2;
    const __nv_bfloat16* Bh = g_Bth[mat] + (size_t)n0 * 256;
    const __nv_bfloat16* Bl = g_Btl[mat] + (size_t)n0 * 256;
    int r = tid >> 1, u = tid & 1;

    // ldmatrix per-lane addresses (offsets within a buffer)
    uint32_t aRow = (uint32_t)(warp_m * 32 + (lane & 7) + ((lane >> 3) & 1) * 8);
    uint32_t aOff = aRow * 80 + ((lane >> 4) & 1) * 16;
    uint32_t bRow = (uint32_t)(warp_n * 64 + (lane & 7) + ((lane >> 4) & 1) * 8);
    uint32_t bOff = bRow * 80 + ((lane >> 3) & 1) * 16;

    // prologue: chunk 0
    {
        float4 f[4];
        const float4* src = (const float4*)(A + (size_t)(m0 + r) * DIN + u * 16);
        f[0] = src[0]; f[1] = src[1]; f[2] = src[2]; f[3] = src[3];
        #pragma unroll
        for (int i = 0; i < 2; ++i) {
            int un = tid + 256 * i;            // 0..511
            int n = un >> 2, uu = un & 3;
            cp_async16(sb + SM_B + n * 80 + uu * 16,         &Bh[n * 256 + uu * 8]);
            cp_async16(sb + SM_B + 10240 + n * 80 + uu * 16, &Bl[n * 256 + uu * 8]);
        }
        CP_COMMIT;
        convert_store_A(smem, 0, tid, f);
        CP_WAIT0;
        __syncthreads();
    }

    for (int kc = 0; kc < 8; ++kc) {
        int cur = kc & 1, nxt = cur ^ 1;
        float4 f[4];
        if (kc < 7) {
            const float4* src = (const float4*)(A + (size_t)(m0 + r) * DIN + (kc + 1) * 32 + u * 16);
            f[0] = src[0]; f[1] = src[1]; f[2] = src[2]; f[3] = src[3];
            #pragma unroll
            for (int i = 0; i < 2; ++i) {
                int un = tid + 256 * i;
                int n = un >> 2, uu = un & 3;
                cp_async16(sb + SM_B + nxt * BBUF + n * 80 + uu * 16,
                           &Bh[n * 256 + (kc + 1) * 32 + uu * 8]);
                cp_async16(sb + SM_B + nxt * BBUF + 10240 + n * 80 + uu * 16,
                           &Bl[n * 256 + (kc + 1) * 32 + uu * 8]);
            }
            CP_COMMIT;
        }

        uint32_t aBase = sb + SM_A + cur * ABUF + aOff;
        uint32_t bBase = sb + SM_B + cur * BBUF + bOff;
        #pragma unroll
        for (int ks = 0; ks < 2; ++ks) {
            uint32_t ah[2][4], al[2][4];
            LDSM4(ah[0], aBase + ks * 32);
            LDSM4(ah[1], aBase + ks * 32 + 1280);            // +16 rows
            LDSM4(al[0], aBase + ks * 32 + 10240);
            LDSM4(al[1], aBase + ks * 32 + 10240 + 1280);
            uint32_t bh[4][4], bl[4][4];
            #pragma unroll
            for (int pr = 0; pr < 4; ++pr) {
                LDSM4(bh[pr], bBase + ks * 32 + pr * 1280);
                LDSM4(bl[pr], bBase + ks * 32 + pr * 1280 + 10240);
            }
            #pragma unroll
            for (int pr = 0; pr < 4; ++pr) {
                #pragma unroll
                for (int sub = 0; sub < 2; ++sub) {
                    int nf = pr * 2 + sub;
                    uint32_t b2h[2] = {bh[pr][2 * sub], bh[pr][2 * sub + 1]};
                    uint32_t b2l[2] = {bl[pr][2 * sub], bl[pr][2 * sub + 1]};
                    #pragma unroll
                    for (int mf = 0; mf < 2; ++mf) {
                        mma16816(acc[mf][nf], ah[mf], b2h);
                        mma16816(acc[mf][nf], al[mf], b2h);
                        mma16816(acc[mf][nf], ah[mf], b2l);
                    }
                }
            }
        }

        if (kc < 7) {
            convert_store_A(smem, nxt, tid, f);
            CP_WAIT0;
            __syncthreads();
        }
    }
}

// ---------------------------------------------------------------------------
// QKV GEMM. grid (125, 3, 2), 256 threads.
// ---------------------------------------------------------------------------
__global__ __launch_bounds__(256, 2) void qkv_mm(const float* __restrict__ x) {
    extern __shared__ char smem[];
    uint32_t sb = smem_u32(smem);
    int tid = threadIdx.x;
    int m0 = blockIdx.x * 128;
    int mat = blockIdx.y;
    int n0 = blockIdx.z * 128;

    float acc[2][8][4];
    #pragma unroll
    for (int mf = 0; mf < 2; ++mf)
        #pragma unroll
        for (int nf = 0; nf < 8; ++nf)
            #pragma unroll
            for (int p = 0; p < 4; ++p) acc[mf][nf][p] = 0.0f;

    gemm_tile(smem, sb, x, m0, mat, n0, tid, acc);

    int lane = tid & 31, w = tid >> 5;
    int warp_m = w & 3, warp_n = w >> 2;
    int qrow = lane >> 2, qcol = lane & 3;
    float* out = mat == 0 ? g_q : mat == 1 ? g_k : g_v;

    #pragma unroll
    for (int mf = 0; mf < 2; ++mf) {
        int r0 = m0 + warp_m * 32 + mf * 16 + qrow;
        #pragma unroll
        for (int nf = 0; nf < 8; ++nf) {
            int c = n0 + warp_n * 64 + nf * 8 + qcol * 2;
            *(float2*)(out + (size_t)r0 * HD + c)       = make_float2(acc[mf][nf][0], acc[mf][nf][1]);
            *(float2*)(out + (size_t)(r0 + 8) * HD + c) = make_float2(acc[mf][nf][2], acc[mf][nf][3]);
        }
    }
}

// ---------------------------------------------------------------------------
// Edge GEMM + fused attention epilogue. grid (2000, 2), 256 threads.
// Each CTA: 128 edges x 128 cols (4 heads).
// ---------------------------------------------------------------------------
__global__ __launch_bounds__(256, 2) void edge_mm(const float* __restrict__ edge_attr,
                                                  const int* __restrict__ ei,
                                                  const float* __restrict__ coords,
                                                  const float* __restrict__ We,
                                                  float* __restrict__ eout) {
    extern __shared__ char smem[];
    uint32_t sb = smem_u32(smem);
    int tid = threadIdx.x;
    int m0 = blockIdx.x * 128;
    int n0 = blockIdx.y * 128;
    int hbase = n0 >> 5;                        // first head of this CTA (4 heads)

    int*   sSrc = (int*)(smem + SM_SRC);
    int*   sDst = (int*)(smem + SM_DST);
    float* sDist = (float*)(smem + SM_DIST);
    float* sAx  = (float*)(smem + SM_AX);       // [128][4]

    if (tid < 128) {
        int s = ei[m0 + tid];
        int d = ei[NEDGES + m0 + tid];
        sSrc[tid] = s; sDst[tid] = d;
        float dx = coords[3 * s + 0] - coords[3 * d + 0];
        float dy = coords[3 * s + 1] - coords[3 * d + 1];
        float dz = coords[3 * s + 2] - coords[3 * d + 2];
        sDist[tid] = 0.1f * sqrtf(dx * dx + dy * dy + dz * dz);
    }
    __syncthreads();

    float acc[2][8][4];
    #pragma unroll
    for (int mf = 0; mf < 2; ++mf)
        #pragma unroll
        for (int nf = 0; nf < 8; ++nf)
            #pragma unroll
            for (int p = 0; p < 4; ++p) acc[mf][nf][p] = 0.0f;

    gemm_tile(smem, sb, edge_attr, m0, 3, n0, tid, acc);

    int lane = tid & 31, w = tid >> 5;
    int warp_m = w & 3, warp_n = w >> 2;
    int qrow = lane >> 2, qcol = lane & 3;
    const float invs = 0.17677669529663687f;   // 1/sqrt(32)

    #pragma unroll
    for (int mf = 0; mf < 2; ++mf) {
        int erow0 = warp_m * 32 + mf * 16 + qrow;
        #pragma unroll
        for (int half = 0; half < 2; ++half) {
            int e = erow0 + 8 * half;
            int src = sSrc[e], dst = sDst[e];
            float de = sDist[e];
            float hsum0 = 0.0f, hsum1 = 0.0f;
            #pragma unroll
            for (int nf = 0; nf < 8; ++nf) {
                int c = n0 + warp_n * 64 + nf * 8 + qcol * 2;
                float2 kk = *(const float2*)(g_k + (size_t)src * HD + c);
                float2 qq = *(const float2*)(g_q + (size_t)dst * HD + c);
                float2 wl = *(const float2*)(We + (size_t)DIN * HD + c);
                float d0 = acc[mf][nf][2 * half + 0];
                float d1 = acc[mf][nf][2 * half + 1];
                float s0 = fminf(5.0f, fmaxf(-5.0f, kk.x * qq.x * invs));
                float s1 = fminf(5.0f, fmaxf(-5.0f, kk.y * qq.y * invs));
                float a0 = s0 * (d0 + de * wl.x);
                float a1 = s1 * (d1 + de * wl.y);
                *(float2*)(eout + (size_t)(m0 + e) * HD + c) = make_float2(a0, a1);
                if (nf < 4) hsum0 += a0 + a1; else hsum1 += a0 + a1;
            }
            hsum0 += __shfl_xor_sync(0xffffffffu, hsum0, 1);
            hsum0 += __shfl_xor_sync(0xffffffffu, hsum0, 2);
            hsum1 += __shfl_xor_sync(0xffffffffu, hsum1, 1);
            hsum1 += __shfl_xor_sync(0xffffffffu, hsum1, 2);
            if (qcol == 0) {
                float ax0 = expf(fminf(5.0f, fmaxf(-5.0f, hsum0)));
                float ax1 = expf(fminf(5.0f, fmaxf(-5.0f, hsum1)));
                int lh0 = 2 * warp_n, lh1 = lh0 + 1;
                sAx[e * 4 + lh0] = ax0;
                sAx[e * 4 + lh1] = ax1;
                atomicAdd(&g_z[(size_t)dst * NH + hbase + lh0], ax0);
                atomicAdd(&g_z[(size_t)dst * NH + hbase + lh1], ax1);
            }
        }
    }
    __syncthreads();

    // scatter wV += v[src] * ax : 512 (edge, local head) pairs over 256 threads
    #pragma unroll
    for (int i = 0; i < 2; ++i) {
        int p = tid + 256 * i;
        int e = p >> 2, lh = p & 3;
        int src = sSrc[e], dst = sDst[e];
        float ax = sAx[e * 4 + lh];
        int h = hbase + lh;
        const float4* v4 = (const float4*)(g_v + (size_t)src * HD + h * 32);
        float* wv = g_wV + (size_t)dst * HD + h * 32;
        #pragma unroll
        for (int j = 0; j < 8; ++j) {
            float4 vv = v4[j];
            atomicAdd(wv + 4 * j + 0, vv.x * ax);
            atomicAdd(wv + 4 * j + 1, vv.y * ax);
            atomicAdd(wv + 4 * j + 2, vv.z * ax);
            atomicAdd(wv + 4 * j + 3, vv.w * ax);
        }
    }
}

// ---------------------------------------------------------------------------
__global__ void finalize_kernel(float* __restrict__ hout) {
    int i = blockIdx.x * blockDim.x + threadIdx.x;
    if (i < NNODES * HD) {
        int n = i >> 8;
        int h = (i & 255) >> 5;
        hout[i] = g_wV[i] / (g_z[n * NH + h] + 1e-6f);
    }
}

// ---------------------------------------------------------------------------
extern "C" void kernel_launch(void* const* d_in, const int* in_sizes, int n_in,
                              void* d_out, int out_size)
{
    const float* x         = (const float*)d_in[0];
    const float* edge_attr = (const float*)d_in[1];
    const int*   ei        = (const int*)d_in[2];
    const float* coords    = (const float*)d_in[3];
    const float* Wq        = (const float*)d_in[4];
    const float* Wk        = (const float*)d_in[5];
    const float* Wv        = (const float*)d_in[6];
    const float* We        = (const float*)d_in[7];

    float* out  = (float*)d_out;
    float* hout = out;
    float* eout = out + (size_t)NNODES * HD;
    float* cout = eout + (size_t)NEDGES * HD;

    static bool attr_set = false;
    if (!attr_set) {
        cudaFuncSetAttribute(qkv_mm,  cudaFuncAttributeMaxDynamicSharedMemorySize, SM_TOTAL);
        cudaFuncSetAttribute(edge_mm, cudaFuncAttributeMaxDynamicSharedMemorySize, SM_TOTAL);
        attr_set = true;
    }

    zero_kernel<<<(NNODES * HD + 255) / 256, 256>>>(coords, cout);
    prep_weights<<<128, 256>>>(Wq, Wk, Wv, We);
    qkv_mm<<<dim3(125, 3, 2), 256, SM_TOTAL>>>(x);
    edge_mm<<<dim3(2000, 2), 256, SM_TOTAL>>>(edge_attr, ei, coords, We, eout);
    finalize_kernel<<<(NNODES * HD + 255) / 256, 256>>>(hout);
}